// round 8
// baseline (speedup 1.0000x reference)
#include <cuda_runtime.h>
#include <math.h>

#define S_LEN 2048
#define D_MODEL 4096
#define NH 32
#define HD 128

// Scratch (static device allocations — allowed; no runtime alloc).
__device__ float g_q[S_LEN * D_MODEL];
__device__ float g_k[S_LEN * D_MODEL];
__device__ float g_v[S_LEN * D_MODEL];
__device__ float g_ctx[S_LEN * D_MODEL];

// ---------------------------------------------------------------------------
// SGEMM: 128x128 tile, BK=8, 256 threads, 8x8 per-thread register tile.
// Double-buffered shared memory: one __syncthreads per k-step, global loads
// for tile k+1 issued before the FMA block on tile k.
// REMAP=1: scatter columns into q/k/v (qkv interleave: n -> (n/3, n%3)).
// ---------------------------------------------------------------------------
template <int REMAP>
__global__ void sgemm_kernel(const float* __restrict__ A,
                             const float* __restrict__ B,
                             float* __restrict__ C,
                             int M, int N, int K) {
    __shared__ float As[2][8][128];   // [buf][k][m] transposed
    __shared__ float Bs[2][8][128];   // [buf][k][n]

    int tid = threadIdx.x;
    int tx = tid & 15;
    int ty = tid >> 4;
    int m0 = blockIdx.y * 128;
    int n0 = blockIdx.x * 128;

    float acc[8][8];
#pragma unroll
    for (int i = 0; i < 8; i++)
#pragma unroll
        for (int j = 0; j < 8; j++) acc[i][j] = 0.f;

    int arow = tid >> 1;
    int akq  = (tid & 1) * 4;
    int brow = tid >> 5;
    int bcol = (tid & 31) * 4;

    const float* Ap = A + (size_t)(m0 + arow) * K + akq;
    const float* Bp = B + (size_t)brow * N + n0 + bcol;

    // Preload tile 0 into buffer 0.
    {
        float4 av = *(const float4*)(Ap);
        As[0][akq + 0][arow] = av.x;
        As[0][akq + 1][arow] = av.y;
        As[0][akq + 2][arow] = av.z;
        As[0][akq + 3][arow] = av.w;
        *(float4*)&Bs[0][brow][bcol] = *(const float4*)(Bp);
    }
    __syncthreads();

    int nk = K / 8;
    for (int kt = 0; kt < nk; kt++) {
        int buf = kt & 1;

        // Issue global loads for the next tile (into registers).
        float4 av, bv;
        bool have_next = (kt + 1 < nk);
        if (have_next) {
            int k0n = (kt + 1) * 8;
            av = *(const float4*)(Ap + k0n);
            bv = *(const float4*)(Bp + (size_t)k0n * N);
        }

        // Compute on current buffer.
#pragma unroll
        for (int kk = 0; kk < 8; kk++) {
            float a[8], b[8];
            *(float4*)(a)     = *(const float4*)&As[buf][kk][ty * 8];
            *(float4*)(a + 4) = *(const float4*)&As[buf][kk][ty * 8 + 4];
            *(float4*)(b)     = *(const float4*)&Bs[buf][kk][tx * 8];
            *(float4*)(b + 4) = *(const float4*)&Bs[buf][kk][tx * 8 + 4];
#pragma unroll
            for (int i = 0; i < 8; i++)
#pragma unroll
                for (int j = 0; j < 8; j++)
                    acc[i][j] += a[i] * b[j];
        }

        // Store next tile into the other buffer.
        if (have_next) {
            int nb = buf ^ 1;
            As[nb][akq + 0][arow] = av.x;
            As[nb][akq + 1][arow] = av.y;
            As[nb][akq + 2][arow] = av.z;
            As[nb][akq + 3][arow] = av.w;
            *(float4*)&Bs[nb][brow][bcol] = bv;
        }
        __syncthreads();
    }

    if (REMAP) {
#pragma unroll
        for (int i = 0; i < 8; i++) {
            int m = m0 + ty * 8 + i;
#pragma unroll
            for (int j = 0; j < 8; j++) {
                int n = n0 + tx * 8 + j;
                int c = n % 3;
                int dix = n / 3;
                float* dst = (c == 0) ? g_q : (c == 1) ? g_k : g_v;
                dst[(size_t)m * D_MODEL + dix] = acc[i][j];
            }
        }
    } else {
#pragma unroll
        for (int i = 0; i < 8; i++) {
            int m = m0 + ty * 8 + i;
            *(float4*)&C[(size_t)m * N + n0 + tx * 8]     = *(float4*)&acc[i][0];
            *(float4*)&C[(size_t)m * N + n0 + tx * 8 + 4] = *(float4*)&acc[i][4];
        }
    }
}

// ---------------------------------------------------------------------------
// RoPE applied in-place to g_q and g_k. One thread per (s, h, i<64) pair.
// ---------------------------------------------------------------------------
__global__ void rope_kernel() {
    int idx = blockIdx.x * blockDim.x + threadIdx.x;
    if (idx >= S_LEN * NH * 64) return;
    int i = idx & 63;
    int h = (idx >> 6) & (NH - 1);
    int s = idx >> 11;

    // inv_freq = 10000^(-2i/128) = exp(-i * ln(10000)/64)
    float inv_freq = expf(-0.14391156831212787f * (float)i);
    float ang = (float)s * inv_freq;
    float sn, c;
    sincosf(ang, &sn, &c);

    size_t base = (size_t)s * D_MODEL + (size_t)h * HD + i;
    float q1 = g_q[base], q2 = g_q[base + 64];
    g_q[base]      = q1 * c - q2 * sn;
    g_q[base + 64] = q2 * c + q1 * sn;
    float k1 = g_k[base], k2 = g_k[base + 64];
    g_k[base]      = k1 * c - k2 * sn;
    g_k[base + 64] = k2 * c + k1 * sn;
}

// ---------------------------------------------------------------------------
// Flash attention (fp32, causal). Block = (q-tile of 64 rows, head).
// 256 threads as 16x16: thread (tx,ty) owns score rows ty*4..+3, cols tx*4..+3
// and output rows ty*4..+3, cols tx*8..+7.
// Smem: Qs/Ks transposed [128][68] (stride 68 floats = 272 B, a multiple of
// 16 B, so every row's 4-float groups are float4-alignable -> LDS.128),
// Vs row-major [64][128], Ps [64][64]. Total 118784 B (dynamic).
// ---------------------------------------------------------------------------
#define QK_STRIDE 68

__global__ void flash_kernel() {
    extern __shared__ float sm[];
    float* Qs = sm;                        // [128][68]  Qs[k*68 + r]
    float* Ks = sm + 128 * QK_STRIDE;      // [128][68]
    float* Vs = Ks + 128 * QK_STRIDE;      // [64][128]  Vs[r*128 + k]
    float* Ps = Vs + 64 * 128;             // [64][64]

    int tid = threadIdx.x;
    int tx = tid & 15;
    int ty = tid >> 4;
    int qt = blockIdx.x;             // q tile index (0..31)
    int h  = blockIdx.y;             // head
    int q0 = qt * 64;

    // Load Q tile transposed.
#pragma unroll
    for (int it = 0; it < 8; it++) {
        int idx = tid + it * 256;
        int r  = idx >> 5;           // 0..63
        int kq = (idx & 31) * 4;     // 0..124
        float4 v = *(const float4*)&g_q[(size_t)(q0 + r) * D_MODEL + h * HD + kq];
        Qs[(kq + 0) * QK_STRIDE + r] = v.x;
        Qs[(kq + 1) * QK_STRIDE + r] = v.y;
        Qs[(kq + 2) * QK_STRIDE + r] = v.z;
        Qs[(kq + 3) * QK_STRIDE + r] = v.w;
    }

    float m_i[4], l_i[4], o[4][8];
#pragma unroll
    for (int i = 0; i < 4; i++) {
        m_i[i] = -INFINITY;
        l_i[i] = 0.f;
#pragma unroll
        for (int j = 0; j < 8; j++) o[i][j] = 0.f;
    }
    __syncthreads();

    const float scale = 0.08838834764831845f;  // 1/sqrt(128)
    int ntiles = qt + 1;

    for (int kt = 0; kt < ntiles; kt++) {
        int k0 = kt * 64;
        // Load K tile (transposed) and V tile (row-major).
#pragma unroll
        for (int it = 0; it < 8; it++) {
            int idx = tid + it * 256;
            int r  = idx >> 5;
            int kq = (idx & 31) * 4;
            size_t gbase = (size_t)(k0 + r) * D_MODEL + h * HD + kq;
            float4 kv = *(const float4*)&g_k[gbase];
            Ks[(kq + 0) * QK_STRIDE + r] = kv.x;
            Ks[(kq + 1) * QK_STRIDE + r] = kv.y;
            Ks[(kq + 2) * QK_STRIDE + r] = kv.z;
            Ks[(kq + 3) * QK_STRIDE + r] = kv.w;
            *(float4*)&Vs[r * 128 + kq] = *(const float4*)&g_v[gbase];
        }
        __syncthreads();

        // S = Q @ K^T (4x4 per thread over k=0..127), float4 smem reads.
        float s[4][4];
#pragma unroll
        for (int i = 0; i < 4; i++)
#pragma unroll
            for (int j = 0; j < 4; j++) s[i][j] = 0.f;

#pragma unroll 4
        for (int kk = 0; kk < 128; kk++) {
            float4 a4 = *(const float4*)&Qs[kk * QK_STRIDE + ty * 4];
            float4 b4 = *(const float4*)&Ks[kk * QK_STRIDE + tx * 4];
            float a[4] = {a4.x, a4.y, a4.z, a4.w};
            float b[4] = {b4.x, b4.y, b4.z, b4.w};
#pragma unroll
            for (int i = 0; i < 4; i++)
#pragma unroll
                for (int j = 0; j < 4; j++) s[i][j] += a[i] * b[j];
        }

        bool diag = (kt == qt);
#pragma unroll
        for (int i = 0; i < 4; i++)
#pragma unroll
            for (int j = 0; j < 4; j++) {
                s[i][j] *= scale;
                if (diag && (tx * 4 + j > ty * 4 + i)) s[i][j] = -INFINITY;
            }

        // Online softmax: per-row reduce across the 16 tx lanes.
#pragma unroll
        for (int i = 0; i < 4; i++) {
            float mx = fmaxf(fmaxf(s[i][0], s[i][1]), fmaxf(s[i][2], s[i][3]));
#pragma unroll
            for (int off = 8; off >= 1; off >>= 1)
                mx = fmaxf(mx, __shfl_xor_sync(0xffffffffu, mx, off));
            float mnew = fmaxf(m_i[i], mx);
            float sum = 0.f;
#pragma unroll
            for (int j = 0; j < 4; j++) {
                s[i][j] = expf(s[i][j] - mnew);
                sum += s[i][j];
            }
#pragma unroll
            for (int off = 8; off >= 1; off >>= 1)
                sum += __shfl_xor_sync(0xffffffffu, sum, off);
            float alpha = expf(m_i[i] - mnew);
            l_i[i] = l_i[i] * alpha + sum;
            m_i[i] = mnew;
#pragma unroll
            for (int j = 0; j < 8; j++) o[i][j] *= alpha;
            // stash P
#pragma unroll
            for (int j = 0; j < 4; j++)
                Ps[(ty * 4 + i) * 64 + tx * 4 + j] = s[i][j];
        }
        __syncthreads();

        // O += P @ V
#pragma unroll 2
        for (int kk = 0; kk < 64; kk++) {
            float4 v0 = *(const float4*)&Vs[kk * 128 + tx * 8];
            float4 v1 = *(const float4*)&Vs[kk * 128 + tx * 8 + 4];
#pragma unroll
            for (int i = 0; i < 4; i++) {
                float pv = Ps[(ty * 4 + i) * 64 + kk];
                o[i][0] += pv * v0.x;
                o[i][1] += pv * v0.y;
                o[i][2] += pv * v0.z;
                o[i][3] += pv * v0.w;
                o[i][4] += pv * v1.x;
                o[i][5] += pv * v1.y;
                o[i][6] += pv * v1.z;
                o[i][7] += pv * v1.w;
            }
        }
        __syncthreads();
    }

    // Normalize and store context.
#pragma unroll
    for (int i = 0; i < 4; i++) {
        float inv = 1.f / l_i[i];
        int r = q0 + ty * 4 + i;
        float4 r0 = make_float4(o[i][0] * inv, o[i][1] * inv, o[i][2] * inv, o[i][3] * inv);
        float4 r1 = make_float4(o[i][4] * inv, o[i][5] * inv, o[i][6] * inv, o[i][7] * inv);
        size_t base = (size_t)r * D_MODEL + h * HD + tx * 8;
        *(float4*)&g_ctx[base]     = r0;
        *(float4*)&g_ctx[base + 4] = r1;
    }
}

#define FLASH_SMEM ((128 * QK_STRIDE * 2 + 64 * 128 + 64 * 64) * 4)

// ---------------------------------------------------------------------------
extern "C" void kernel_launch(void* const* d_in, const int* in_sizes, int n_in,
                              void* d_out, int out_size) {
    const float* hidden = (const float*)d_in[0];
    // d_in[1] = attention_mask (causal, recomputed analytically)
    // d_in[2] = position_ids (0..S-1, recomputed analytically)
    const float* Wqkv = (const float*)d_in[3];
    const float* Wo   = (const float*)d_in[4];
    float* out = (float*)d_out;

    // 1) QKV projection with interleave remap into g_q/g_k/g_v
    dim3 g1(12288 / 128, S_LEN / 128);
    sgemm_kernel<1><<<g1, 256>>>(hidden, Wqkv, nullptr, S_LEN, 3 * D_MODEL, D_MODEL);

    // 2) RoPE in place
    int nrope = S_LEN * NH * 64;
    rope_kernel<<<(nrope + 255) / 256, 256>>>();

    // 3) Flash attention
    cudaFuncSetAttribute(flash_kernel, cudaFuncAttributeMaxDynamicSharedMemorySize, FLASH_SMEM);
    dim3 gf(S_LEN / 64, NH);
    flash_kernel<<<gf, 256, FLASH_SMEM>>>();

    // 4) Output projection
    void* pctx = nullptr;
    cudaGetSymbolAddress(&pctx, g_ctx);
    dim3 g2(D_MODEL / 128, S_LEN / 128);
    sgemm_kernel<0><<<g2, 256>>>((const float*)pctx, Wo, out, S_LEN, D_MODEL, D_MODEL);
}

// round 12
// speedup vs baseline: 1.8520x; 1.8520x over previous
#include <cuda_runtime.h>
#include <cuda_bf16.h>
#include <math.h>
#include <stdint.h>

#define S_LEN 2048
#define D_MODEL 4096
#define NH 32
#define HD 128

// ---------------------------------------------------------------------------
// Static device scratch (no runtime allocation).
// ---------------------------------------------------------------------------
__device__ float g_q[S_LEN * D_MODEL];
__device__ float g_k[S_LEN * D_MODEL];
__device__ float g_v[S_LEN * D_MODEL];
__device__ float g_ctx[S_LEN * D_MODEL];

__device__ __nv_bfloat16 g_ah[S_LEN * D_MODEL];             // hidden hi
__device__ __nv_bfloat16 g_al[S_LEN * D_MODEL];             // hidden lo
__device__ __nv_bfloat16 g_cth[S_LEN * D_MODEL];            // ctx hi
__device__ __nv_bfloat16 g_ctl[S_LEN * D_MODEL];            // ctx lo
__device__ __nv_bfloat16 g_wqkvT_h[3 * D_MODEL * D_MODEL];  // [12288][4096] K-major
__device__ __nv_bfloat16 g_wqkvT_l[3 * D_MODEL * D_MODEL];
__device__ __nv_bfloat16 g_woT_h[D_MODEL * D_MODEL];        // [4096][4096] K-major
__device__ __nv_bfloat16 g_woT_l[D_MODEL * D_MODEL];

// ---------------------------------------------------------------------------
// Baseline-PTX helpers (sm_80-era features; compile for compute_103).
// ---------------------------------------------------------------------------
__device__ __forceinline__ uint32_t smem_u32(const void* p) {
    uint32_t a;
    asm("{ .reg .u64 t; cvta.to.shared.u64 t, %1; cvt.u32.u64 %0, t; }" : "=r"(a) : "l"(p));
    return a;
}

__device__ __forceinline__ void cpa16(uint32_t saddr, const void* g) {
    asm volatile("cp.async.cg.shared.global [%0], [%1], 16;" :: "r"(saddr), "l"(g));
}

__device__ __forceinline__ void ldsm_x4(uint32_t& r0, uint32_t& r1, uint32_t& r2, uint32_t& r3,
                                        uint32_t addr) {
    asm volatile("ldmatrix.sync.aligned.m8n8.x4.shared.b16 {%0,%1,%2,%3}, [%4];"
                 : "=r"(r0), "=r"(r1), "=r"(r2), "=r"(r3) : "r"(addr));
}

__device__ __forceinline__ void ldsm_x2(uint32_t& r0, uint32_t& r1, uint32_t addr) {
    asm volatile("ldmatrix.sync.aligned.m8n8.x2.shared.b16 {%0,%1}, [%2];"
                 : "=r"(r0), "=r"(r1) : "r"(addr));
}

__device__ __forceinline__ void mma16816(float* c, const uint32_t* a, const uint32_t* b) {
    asm volatile(
        "mma.sync.aligned.m16n8k16.row.col.f32.bf16.bf16.f32 "
        "{%0,%1,%2,%3}, {%4,%5,%6,%7}, {%8,%9}, {%0,%1,%2,%3};"
        : "+f"(c[0]), "+f"(c[1]), "+f"(c[2]), "+f"(c[3])
        : "r"(a[0]), "r"(a[1]), "r"(a[2]), "r"(a[3]), "r"(b[0]), "r"(b[1]));
}

// ---------------------------------------------------------------------------
// Split fp32 -> bf16 hi/lo (same layout).
// ---------------------------------------------------------------------------
__global__ void split_rows_kernel(const float* __restrict__ src,
                                  __nv_bfloat16* __restrict__ hi,
                                  __nv_bfloat16* __restrict__ lo, int n4) {
    int i = blockIdx.x * blockDim.x + threadIdx.x;
    if (i >= n4) return;
    float4 v = ((const float4*)src)[i];
    __nv_bfloat16 h0 = __float2bfloat16(v.x);
    __nv_bfloat16 h1 = __float2bfloat16(v.y);
    __nv_bfloat16 h2 = __float2bfloat16(v.z);
    __nv_bfloat16 h3 = __float2bfloat16(v.w);
    __nv_bfloat16 l0 = __float2bfloat16(v.x - __bfloat162float(h0));
    __nv_bfloat16 l1 = __float2bfloat16(v.y - __bfloat162float(h1));
    __nv_bfloat16 l2 = __float2bfloat16(v.z - __bfloat162float(h2));
    __nv_bfloat16 l3 = __float2bfloat16(v.w - __bfloat162float(h3));
    ((__nv_bfloat162*)hi)[i * 2 + 0] = __halves2bfloat162(h0, h1);
    ((__nv_bfloat162*)hi)[i * 2 + 1] = __halves2bfloat162(h2, h3);
    ((__nv_bfloat162*)lo)[i * 2 + 0] = __halves2bfloat162(l0, l1);
    ((__nv_bfloat162*)lo)[i * 2 + 1] = __halves2bfloat162(l2, l3);
}

// ---------------------------------------------------------------------------
// Split + transpose: src fp32 [R x C] -> hi/lo bf16 [C x R] (K-major).
// ---------------------------------------------------------------------------
__global__ void split_transpose_kernel(const float* __restrict__ src,
                                       __nv_bfloat16* __restrict__ hi,
                                       __nv_bfloat16* __restrict__ lo,
                                       int R, int C) {
    __shared__ float t[32][33];
    int c0 = blockIdx.x * 32, r0 = blockIdx.y * 32;
    int tx = threadIdx.x, ty = threadIdx.y;
#pragma unroll
    for (int i = 0; i < 4; i++)
        t[ty + i * 8][tx] = src[(size_t)(r0 + ty + i * 8) * C + c0 + tx];
    __syncthreads();
#pragma unroll
    for (int i = 0; i < 4; i++) {
        float v = t[tx][ty + i * 8];
        __nv_bfloat16 h = __float2bfloat16(v);
        __nv_bfloat16 l = __float2bfloat16(v - __bfloat162float(h));
        size_t o = (size_t)(c0 + ty + i * 8) * R + r0 + tx;
        hi[o] = h;
        lo[o] = l;
    }
}

// ---------------------------------------------------------------------------
// Split-bf16 HMMA GEMM: C[m,n] = sum_k A[m,k]*B[n,k], fp32 accum.
// CTA 128x128, 8 warps (2m x 4n), warp tile 64x32, BK=32, cp.async double buf.
// SMEM per buf: Ah,Al,Bh,Bl each 128 rows x 40 bf16 pitch (80B) = 10240B.
// 3-term: AhBh + AhBl + AlBh (AlBl ~2^-18, dropped).
// REMAP=1: scatter col n -> (n/3 , n%3) into g_q/g_k/g_v.
// ---------------------------------------------------------------------------
#define BKC 32
#define PITCH 40
#define TERM_BYTES (128 * PITCH * 2)   // 10240
#define BUF_BYTES (4 * TERM_BYTES)     // 40960
#define GEMM_SMEM (2 * BUF_BYTES)      // 81920

__device__ __forceinline__ void issue_chunk(uint32_t base, int tid,
                                            const __nv_bfloat16* Ah, const __nv_bfloat16* Al,
                                            const __nv_bfloat16* Bh, const __nv_bfloat16* Bl,
                                            int m0, int n0, int k0, int K) {
#pragma unroll
    for (int h = 0; h < 2; h++) {
        int s = tid + h * 256;         // 0..511
        int r = s >> 2, c = s & 3;     // row 0..127, 16B seg 0..3
        uint32_t so = (uint32_t)(r * PITCH + c * 8) * 2;
        size_t ga = (size_t)(m0 + r) * K + k0 + c * 8;
        size_t gb = (size_t)(n0 + r) * K + k0 + c * 8;
        cpa16(base + 0 * TERM_BYTES + so, Ah + ga);
        cpa16(base + 1 * TERM_BYTES + so, Al + ga);
        cpa16(base + 2 * TERM_BYTES + so, Bh + gb);
        cpa16(base + 3 * TERM_BYTES + so, Bl + gb);
    }
    asm volatile("cp.async.commit_group;" ::: "memory");
}

template <int REMAP>
__global__ void __launch_bounds__(256) gemm_mma_kernel(
    const __nv_bfloat16* __restrict__ Ah, const __nv_bfloat16* __restrict__ Al,
    const __nv_bfloat16* __restrict__ Bh, const __nv_bfloat16* __restrict__ Bl,
    float* __restrict__ C) {
    extern __shared__ char smem[];
    uint32_t sb = smem_u32(smem);
    int tid = threadIdx.x;
    int lane = tid & 31;
    int wid = tid >> 5;
    int wm = wid >> 2;             // 0..1
    int wn = wid & 3;              // 0..3
    int MB = wm * 64, NB = wn * 32;
    int m0 = blockIdx.x * 128, n0 = blockIdx.y * 128;
    const int K = 4096, NK = K / BKC;

    float acc[4][4][4];
#pragma unroll
    for (int i = 0; i < 4; i++)
#pragma unroll
        for (int j = 0; j < 4; j++)
#pragma unroll
            for (int r = 0; r < 4; r++) acc[i][j][r] = 0.f;

    // ldmatrix lane address components
    int a_r = (lane & 7) | (((lane >> 3) & 1) << 3);   // row within m16
    int a_k = (lane >> 4) << 3;                        // 0 or 8 within k16
    int b_r = lane & 7;                                // n row within n8
    int b_k = ((lane >> 3) & 1) << 3;                  // 0 or 8 within k16

    issue_chunk(sb, tid, Ah, Al, Bh, Bl, m0, n0, 0, K);

    int buf = 0;
    for (int kc = 0; kc < NK; kc++) {
        if (kc + 1 < NK) {
            issue_chunk(sb + (uint32_t)(buf ^ 1) * BUF_BYTES, tid, Ah, Al, Bh, Bl,
                        m0, n0, (kc + 1) * BKC, K);
            asm volatile("cp.async.wait_group 1;" ::: "memory");
        } else {
            asm volatile("cp.async.wait_group 0;" ::: "memory");
        }
        __syncthreads();

        uint32_t bb = sb + (uint32_t)buf * BUF_BYTES;
#pragma unroll
        for (int kk = 0; kk < 2; kk++) {
            uint32_t Afh[4][4], Afl[4][4], Bfh[4][2], Bfl[4][2];
#pragma unroll
            for (int mt = 0; mt < 4; mt++) {
                uint32_t ao = (uint32_t)((MB + mt * 16 + a_r) * PITCH + kk * 16 + a_k) * 2;
                ldsm_x4(Afh[mt][0], Afh[mt][1], Afh[mt][2], Afh[mt][3], bb + 0 * TERM_BYTES + ao);
                ldsm_x4(Afl[mt][0], Afl[mt][1], Afl[mt][2], Afl[mt][3], bb + 1 * TERM_BYTES + ao);
            }
#pragma unroll
            for (int nt = 0; nt < 4; nt++) {
                uint32_t bo = (uint32_t)((NB + nt * 8 + b_r) * PITCH + kk * 16 + b_k) * 2;
                ldsm_x2(Bfh[nt][0], Bfh[nt][1], bb + 2 * TERM_BYTES + bo);
                ldsm_x2(Bfl[nt][0], Bfl[nt][1], bb + 3 * TERM_BYTES + bo);
            }
#pragma unroll
            for (int mt = 0; mt < 4; mt++)
#pragma unroll
                for (int nt = 0; nt < 4; nt++) {
                    mma16816(acc[mt][nt], Afh[mt], Bfh[nt]);
                    mma16816(acc[mt][nt], Afh[mt], Bfl[nt]);
                    mma16816(acc[mt][nt], Afl[mt], Bfh[nt]);
                }
        }
        __syncthreads();
        buf ^= 1;
    }

    // Epilogue: C fragment c0,c1 = (row g, cols tig*2,+1); c2,c3 = row g+8.
    int g = lane >> 2, tig = lane & 3;
#pragma unroll
    for (int mt = 0; mt < 4; mt++)
#pragma unroll
        for (int nt = 0; nt < 4; nt++) {
            int row0 = m0 + MB + mt * 16 + g;
            int row1 = row0 + 8;
            int cb = n0 + NB + nt * 8 + tig * 2;
#pragma unroll
            for (int e = 0; e < 2; e++) {
                int n = cb + e;
                float v0 = acc[mt][nt][e];      // row0
                float v1 = acc[mt][nt][2 + e];  // row1
                if (REMAP) {
                    int c = n % 3;
                    int ix = n / 3;
                    float* dst = (c == 0) ? g_q : (c == 1) ? g_k : g_v;
                    dst[(size_t)row0 * D_MODEL + ix] = v0;
                    dst[(size_t)row1 * D_MODEL + ix] = v1;
                } else {
                    C[(size_t)row0 * D_MODEL + n] = v0;
                    C[(size_t)row1 * D_MODEL + n] = v1;
                }
            }
        }
}

// ---------------------------------------------------------------------------
// RoPE applied in-place to g_q and g_k.
// ---------------------------------------------------------------------------
__global__ void rope_kernel() {
    int idx = blockIdx.x * blockDim.x + threadIdx.x;
    if (idx >= S_LEN * NH * 64) return;
    int i = idx & 63;
    int h = (idx >> 6) & (NH - 1);
    int s = idx >> 11;
    float inv_freq = expf(-0.14391156831212787f * (float)i);
    float ang = (float)s * inv_freq;
    float sn, c;
    sincosf(ang, &sn, &c);
    size_t base = (size_t)s * D_MODEL + (size_t)h * HD + i;
    float q1 = g_q[base], q2 = g_q[base + 64];
    g_q[base]      = q1 * c - q2 * sn;
    g_q[base + 64] = q2 * c + q1 * sn;
    float k1 = g_k[base], k2 = g_k[base + 64];
    g_k[base]      = k1 * c - k2 * sn;
    g_k[base + 64] = k2 * c + k1 * sn;
}

// ---------------------------------------------------------------------------
// Flash attention (fp32, causal) — unchanged from measured baseline.
// ---------------------------------------------------------------------------
#define QK_STRIDE 68

__global__ void flash_kernel() {
    extern __shared__ float sm[];
    float* Qs = sm;
    float* Ks = sm + 128 * QK_STRIDE;
    float* Vs = Ks + 128 * QK_STRIDE;
    float* Ps = Vs + 64 * 128;

    int tid = threadIdx.x;
    int tx = tid & 15;
    int ty = tid >> 4;
    int qt = blockIdx.x;
    int h  = blockIdx.y;
    int q0 = qt * 64;

#pragma unroll
    for (int it = 0; it < 8; it++) {
        int idx = tid + it * 256;
        int r  = idx >> 5;
        int kq = (idx & 31) * 4;
        float4 v = *(const float4*)&g_q[(size_t)(q0 + r) * D_MODEL + h * HD + kq];
        Qs[(kq + 0) * QK_STRIDE + r] = v.x;
        Qs[(kq + 1) * QK_STRIDE + r] = v.y;
        Qs[(kq + 2) * QK_STRIDE + r] = v.z;
        Qs[(kq + 3) * QK_STRIDE + r] = v.w;
    }

    float m_i[4], l_i[4], o[4][8];
#pragma unroll
    for (int i = 0; i < 4; i++) {
        m_i[i] = -INFINITY;
        l_i[i] = 0.f;
#pragma unroll
        for (int j = 0; j < 8; j++) o[i][j] = 0.f;
    }
    __syncthreads();

    const float scale = 0.08838834764831845f;
    int ntiles = qt + 1;

    for (int kt = 0; kt < ntiles; kt++) {
        int k0 = kt * 64;
#pragma unroll
        for (int it = 0; it < 8; it++) {
            int idx = tid + it * 256;
            int r  = idx >> 5;
            int kq = (idx & 31) * 4;
            size_t gbase = (size_t)(k0 + r) * D_MODEL + h * HD + kq;
            float4 kv = *(const float4*)&g_k[gbase];
            Ks[(kq + 0) * QK_STRIDE + r] = kv.x;
            Ks[(kq + 1) * QK_STRIDE + r] = kv.y;
            Ks[(kq + 2) * QK_STRIDE + r] = kv.z;
            Ks[(kq + 3) * QK_STRIDE + r] = kv.w;
            *(float4*)&Vs[r * 128 + kq] = *(const float4*)&g_v[gbase];
        }
        __syncthreads();

        float s[4][4];
#pragma unroll
        for (int i = 0; i < 4; i++)
#pragma unroll
            for (int j = 0; j < 4; j++) s[i][j] = 0.f;

#pragma unroll 4
        for (int kk = 0; kk < 128; kk++) {
            float4 a4 = *(const float4*)&Qs[kk * QK_STRIDE + ty * 4];
            float4 b4 = *(const float4*)&Ks[kk * QK_STRIDE + tx * 4];
            float a[4] = {a4.x, a4.y, a4.z, a4.w};
            float b[4] = {b4.x, b4.y, b4.z, b4.w};
#pragma unroll
            for (int i = 0; i < 4; i++)
#pragma unroll
                for (int j = 0; j < 4; j++) s[i][j] += a[i] * b[j];
        }

        bool diag = (kt == qt);
#pragma unroll
        for (int i = 0; i < 4; i++)
#pragma unroll
            for (int j = 0; j < 4; j++) {
                s[i][j] *= scale;
                if (diag && (tx * 4 + j > ty * 4 + i)) s[i][j] = -INFINITY;
            }

#pragma unroll
        for (int i = 0; i < 4; i++) {
            float mx = fmaxf(fmaxf(s[i][0], s[i][1]), fmaxf(s[i][2], s[i][3]));
#pragma unroll
            for (int off = 8; off >= 1; off >>= 1)
                mx = fmaxf(mx, __shfl_xor_sync(0xffffffffu, mx, off));
            float mnew = fmaxf(m_i[i], mx);
            float sum = 0.f;
#pragma unroll
            for (int j = 0; j < 4; j++) {
                s[i][j] = expf(s[i][j] - mnew);
                sum += s[i][j];
            }
#pragma unroll
            for (int off = 8; off >= 1; off >>= 1)
                sum += __shfl_xor_sync(0xffffffffu, sum, off);
            float alpha = expf(m_i[i] - mnew);
            l_i[i] = l_i[i] * alpha + sum;
            m_i[i] = mnew;
#pragma unroll
            for (int j = 0; j < 8; j++) o[i][j] *= alpha;
#pragma unroll
            for (int j = 0; j < 4; j++)
                Ps[(ty * 4 + i) * 64 + tx * 4 + j] = s[i][j];
        }
        __syncthreads();

#pragma unroll 2
        for (int kk = 0; kk < 64; kk++) {
            float4 v0 = *(const float4*)&Vs[kk * 128 + tx * 8];
            float4 v1 = *(const float4*)&Vs[kk * 128 + tx * 8 + 4];
#pragma unroll
            for (int i = 0; i < 4; i++) {
                float pv = Ps[(ty * 4 + i) * 64 + kk];
                o[i][0] += pv * v0.x;
                o[i][1] += pv * v0.y;
                o[i][2] += pv * v0.z;
                o[i][3] += pv * v0.w;
                o[i][4] += pv * v1.x;
                o[i][5] += pv * v1.y;
                o[i][6] += pv * v1.z;
                o[i][7] += pv * v1.w;
            }
        }
        __syncthreads();
    }

#pragma unroll
    for (int i = 0; i < 4; i++) {
        float inv = 1.f / l_i[i];
        int r = q0 + ty * 4 + i;
        float4 r0 = make_float4(o[i][0] * inv, o[i][1] * inv, o[i][2] * inv, o[i][3] * inv);
        float4 r1 = make_float4(o[i][4] * inv, o[i][5] * inv, o[i][6] * inv, o[i][7] * inv);
        size_t base = (size_t)r * D_MODEL + h * HD + tx * 8;
        *(float4*)&g_ctx[base]     = r0;
        *(float4*)&g_ctx[base + 4] = r1;
    }
}

#define FLASH_SMEM ((128 * QK_STRIDE * 2 + 64 * 128 + 64 * 64) * 4)

// ---------------------------------------------------------------------------
extern "C" void kernel_launch(void* const* d_in, const int* in_sizes, int n_in,
                              void* d_out, int out_size) {
    const float* hidden = (const float*)d_in[0];
    const float* Wqkv = (const float*)d_in[3];
    const float* Wo   = (const float*)d_in[4];
    float* out = (float*)d_out;

    cudaFuncSetAttribute(gemm_mma_kernel<1>, cudaFuncAttributeMaxDynamicSharedMemorySize, GEMM_SMEM);
    cudaFuncSetAttribute(gemm_mma_kernel<0>, cudaFuncAttributeMaxDynamicSharedMemorySize, GEMM_SMEM);
    cudaFuncSetAttribute(flash_kernel, cudaFuncAttributeMaxDynamicSharedMemorySize, FLASH_SMEM);

    void *p_ah, *p_al, *p_wqh, *p_wql, *p_woh, *p_wol, *p_cth, *p_ctl, *p_ctx;
    cudaGetSymbolAddress(&p_ah, g_ah);
    cudaGetSymbolAddress(&p_al, g_al);
    cudaGetSymbolAddress(&p_wqh, g_wqkvT_h);
    cudaGetSymbolAddress(&p_wql, g_wqkvT_l);
    cudaGetSymbolAddress(&p_woh, g_woT_h);
    cudaGetSymbolAddress(&p_wol, g_woT_l);
    cudaGetSymbolAddress(&p_cth, g_cth);
    cudaGetSymbolAddress(&p_ctl, g_ctl);
    cudaGetSymbolAddress(&p_ctx, g_ctx);

    // 1) split hidden, split+transpose weights into K-major bf16 hi/lo
    split_rows_kernel<<<(S_LEN * D_MODEL / 4 + 255) / 256, 256>>>(
        hidden, (__nv_bfloat16*)p_ah, (__nv_bfloat16*)p_al, S_LEN * D_MODEL / 4);
    split_transpose_kernel<<<dim3(3 * D_MODEL / 32, D_MODEL / 32), dim3(32, 8)>>>(
        Wqkv, (__nv_bfloat16*)p_wqh, (__nv_bfloat16*)p_wql, D_MODEL, 3 * D_MODEL);
    split_transpose_kernel<<<dim3(D_MODEL / 32, D_MODEL / 32), dim3(32, 8)>>>(
        Wo, (__nv_bfloat16*)p_woh, (__nv_bfloat16*)p_wol, D_MODEL, D_MODEL);

    // 2) QKV projection (HMMA, remap into g_q/g_k/g_v)
    gemm_mma_kernel<1><<<dim3(16, 96), 256, GEMM_SMEM>>>(
        (const __nv_bfloat16*)p_ah, (const __nv_bfloat16*)p_al,
        (const __nv_bfloat16*)p_wqh, (const __nv_bfloat16*)p_wql, nullptr);

    // 3) RoPE
    rope_kernel<<<(S_LEN * NH * 64 + 255) / 256, 256>>>();

    // 4) Flash attention
    flash_kernel<<<dim3(S_LEN / 64, NH), 256, FLASH_SMEM>>>();

    // 5) split ctx, output projection (HMMA)
    split_rows_kernel<<<(S_LEN * D_MODEL / 4 + 255) / 256, 256>>>(
        (const float*)p_ctx, (__nv_bfloat16*)p_cth, (__nv_bfloat16*)p_ctl, S_LEN * D_MODEL / 4);
    gemm_mma_kernel<0><<<dim3(16, 32), 256, GEMM_SMEM>>>(
        (const __nv_bfloat16*)p_cth, (const __nv_bfloat16*)p_ctl,
        (const __nv_bfloat16*)p_woh, (const __nv_bfloat16*)p_wol, out);
}

// round 17
// speedup vs baseline: 2.4353x; 1.3149x over previous
#include <cuda_runtime.h>
#include <cuda_bf16.h>
#include <math.h>
#include <stdint.h>

#define S_LEN 2048
#define D_MODEL 4096
#define NH 32
#define HD 128

// ---------------------------------------------------------------------------
// Static device scratch (no runtime allocation).
// ---------------------------------------------------------------------------
__device__ float g_q[S_LEN * D_MODEL];
__device__ float g_k[S_LEN * D_MODEL];
__device__ float g_v[S_LEN * D_MODEL];
__device__ float g_ctx[S_LEN * D_MODEL];

__device__ __nv_bfloat16 g_ah[S_LEN * D_MODEL];
__device__ __nv_bfloat16 g_al[S_LEN * D_MODEL];
__device__ __nv_bfloat16 g_cth[S_LEN * D_MODEL];
__device__ __nv_bfloat16 g_ctl[S_LEN * D_MODEL];
__device__ __nv_bfloat16 g_wqkvT_h[3 * D_MODEL * D_MODEL];
__device__ __nv_bfloat16 g_wqkvT_l[3 * D_MODEL * D_MODEL];
__device__ __nv_bfloat16 g_woT_h[D_MODEL * D_MODEL];
__device__ __nv_bfloat16 g_woT_l[D_MODEL * D_MODEL];

// flash operands (bf16 hi/lo splits)
__device__ __nv_bfloat16 g_qh[S_LEN * D_MODEL];
__device__ __nv_bfloat16 g_ql[S_LEN * D_MODEL];
__device__ __nv_bfloat16 g_kh[S_LEN * D_MODEL];
__device__ __nv_bfloat16 g_kl[S_LEN * D_MODEL];
__device__ __nv_bfloat16 g_vh[S_LEN * D_MODEL];
__device__ __nv_bfloat16 g_vl[S_LEN * D_MODEL];

// ---------------------------------------------------------------------------
// PTX helpers (sm_80-baseline features only).
// ---------------------------------------------------------------------------
__device__ __forceinline__ uint32_t smem_u32(const void* p) {
    uint32_t a;
    asm("{ .reg .u64 t; cvta.to.shared.u64 t, %1; cvt.u32.u64 %0, t; }" : "=r"(a) : "l"(p));
    return a;
}

__device__ __forceinline__ void cpa16(uint32_t saddr, const void* g) {
    asm volatile("cp.async.cg.shared.global [%0], [%1], 16;" :: "r"(saddr), "l"(g));
}

__device__ __forceinline__ void ldsm_x4(uint32_t& r0, uint32_t& r1, uint32_t& r2, uint32_t& r3,
                                        uint32_t addr) {
    asm volatile("ldmatrix.sync.aligned.m8n8.x4.shared.b16 {%0,%1,%2,%3}, [%4];"
                 : "=r"(r0), "=r"(r1), "=r"(r2), "=r"(r3) : "r"(addr));
}

__device__ __forceinline__ void ldsm_x2(uint32_t& r0, uint32_t& r1, uint32_t addr) {
    asm volatile("ldmatrix.sync.aligned.m8n8.x2.shared.b16 {%0,%1}, [%2];"
                 : "=r"(r0), "=r"(r1) : "r"(addr));
}

__device__ __forceinline__ void ldsm_x2t(uint32_t& r0, uint32_t& r1, uint32_t addr) {
    asm volatile("ldmatrix.sync.aligned.m8n8.x2.trans.shared.b16 {%0,%1}, [%2];"
                 : "=r"(r0), "=r"(r1) : "r"(addr));
}

__device__ __forceinline__ void mma16816(float* c, const uint32_t* a, const uint32_t* b) {
    asm volatile(
        "mma.sync.aligned.m16n8k16.row.col.f32.bf16.bf16.f32 "
        "{%0,%1,%2,%3}, {%4,%5,%6,%7}, {%8,%9}, {%0,%1,%2,%3};"
        : "+f"(c[0]), "+f"(c[1]), "+f"(c[2]), "+f"(c[3])
        : "r"(a[0]), "r"(a[1]), "r"(a[2]), "r"(a[3]), "r"(b[0]), "r"(b[1]));
}

// ---------------------------------------------------------------------------
// Split fp32 -> bf16 hi/lo (same layout).
// ---------------------------------------------------------------------------
__global__ void split_rows_kernel(const float* __restrict__ src,
                                  __nv_bfloat16* __restrict__ hi,
                                  __nv_bfloat16* __restrict__ lo, int n4) {
    int i = blockIdx.x * blockDim.x + threadIdx.x;
    if (i >= n4) return;
    float4 v = ((const float4*)src)[i];
    __nv_bfloat16 h0 = __float2bfloat16(v.x);
    __nv_bfloat16 h1 = __float2bfloat16(v.y);
    __nv_bfloat16 h2 = __float2bfloat16(v.z);
    __nv_bfloat16 h3 = __float2bfloat16(v.w);
    __nv_bfloat16 l0 = __float2bfloat16(v.x - __bfloat162float(h0));
    __nv_bfloat16 l1 = __float2bfloat16(v.y - __bfloat162float(h1));
    __nv_bfloat16 l2 = __float2bfloat16(v.z - __bfloat162float(h2));
    __nv_bfloat16 l3 = __float2bfloat16(v.w - __bfloat162float(h3));
    ((__nv_bfloat162*)hi)[i * 2 + 0] = __halves2bfloat162(h0, h1);
    ((__nv_bfloat162*)hi)[i * 2 + 1] = __halves2bfloat162(h2, h3);
    ((__nv_bfloat162*)lo)[i * 2 + 0] = __halves2bfloat162(l0, l1);
    ((__nv_bfloat162*)lo)[i * 2 + 1] = __halves2bfloat162(l2, l3);
}

// ---------------------------------------------------------------------------
// Split + transpose: src fp32 [R x C] -> hi/lo bf16 [C x R] (K-major).
// ---------------------------------------------------------------------------
__global__ void split_transpose_kernel(const float* __restrict__ src,
                                       __nv_bfloat16* __restrict__ hi,
                                       __nv_bfloat16* __restrict__ lo,
                                       int R, int C) {
    __shared__ float t[32][33];
    int c0 = blockIdx.x * 32, r0 = blockIdx.y * 32;
    int tx = threadIdx.x, ty = threadIdx.y;
#pragma unroll
    for (int i = 0; i < 4; i++)
        t[ty + i * 8][tx] = src[(size_t)(r0 + ty + i * 8) * C + c0 + tx];
    __syncthreads();
#pragma unroll
    for (int i = 0; i < 4; i++) {
        float v = t[tx][ty + i * 8];
        __nv_bfloat16 h = __float2bfloat16(v);
        __nv_bfloat16 l = __float2bfloat16(v - __bfloat162float(h));
        size_t o = (size_t)(c0 + ty + i * 8) * R + r0 + tx;
        hi[o] = h;
        lo[o] = l;
    }
}

// ---------------------------------------------------------------------------
// Split-bf16 HMMA GEMM (measured-correct R12 version).
// ---------------------------------------------------------------------------
#define BKC 32
#define PITCH 40
#define TERM_BYTES (128 * PITCH * 2)
#define BUF_BYTES (4 * TERM_BYTES)
#define GEMM_SMEM (2 * BUF_BYTES)

__device__ __forceinline__ void issue_chunk(uint32_t base, int tid,
                                            const __nv_bfloat16* Ah, const __nv_bfloat16* Al,
                                            const __nv_bfloat16* Bh, const __nv_bfloat16* Bl,
                                            int m0, int n0, int k0, int K) {
#pragma unroll
    for (int h = 0; h < 2; h++) {
        int s = tid + h * 256;
        int r = s >> 2, c = s & 3;
        uint32_t so = (uint32_t)(r * PITCH + c * 8) * 2;
        size_t ga = (size_t)(m0 + r) * K + k0 + c * 8;
        size_t gb = (size_t)(n0 + r) * K + k0 + c * 8;
        cpa16(base + 0 * TERM_BYTES + so, Ah + ga);
        cpa16(base + 1 * TERM_BYTES + so, Al + ga);
        cpa16(base + 2 * TERM_BYTES + so, Bh + gb);
        cpa16(base + 3 * TERM_BYTES + so, Bl + gb);
    }
    asm volatile("cp.async.commit_group;" ::: "memory");
}

template <int REMAP>
__global__ void __launch_bounds__(256) gemm_mma_kernel(
    const __nv_bfloat16* __restrict__ Ah, const __nv_bfloat16* __restrict__ Al,
    const __nv_bfloat16* __restrict__ Bh, const __nv_bfloat16* __restrict__ Bl,
    float* __restrict__ C) {
    extern __shared__ char smem[];
    uint32_t sb = smem_u32(smem);
    int tid = threadIdx.x;
    int lane = tid & 31;
    int wid = tid >> 5;
    int wm = wid >> 2;
    int wn = wid & 3;
    int MB = wm * 64, NB = wn * 32;
    int m0 = blockIdx.x * 128, n0 = blockIdx.y * 128;
    const int K = 4096, NK = K / BKC;

    float acc[4][4][4];
#pragma unroll
    for (int i = 0; i < 4; i++)
#pragma unroll
        for (int j = 0; j < 4; j++)
#pragma unroll
            for (int r = 0; r < 4; r++) acc[i][j][r] = 0.f;

    int a_r = (lane & 7) | (((lane >> 3) & 1) << 3);
    int a_k = (lane >> 4) << 3;
    int b_r = lane & 7;
    int b_k = ((lane >> 3) & 1) << 3;

    issue_chunk(sb, tid, Ah, Al, Bh, Bl, m0, n0, 0, K);

    int buf = 0;
    for (int kc = 0; kc < NK; kc++) {
        if (kc + 1 < NK) {
            issue_chunk(sb + (uint32_t)(buf ^ 1) * BUF_BYTES, tid, Ah, Al, Bh, Bl,
                        m0, n0, (kc + 1) * BKC, K);
            asm volatile("cp.async.wait_group 1;" ::: "memory");
        } else {
            asm volatile("cp.async.wait_group 0;" ::: "memory");
        }
        __syncthreads();

        uint32_t bb = sb + (uint32_t)buf * BUF_BYTES;
#pragma unroll
        for (int kk = 0; kk < 2; kk++) {
            uint32_t Afh[4][4], Afl[4][4], Bfh[4][2], Bfl[4][2];
#pragma unroll
            for (int mt = 0; mt < 4; mt++) {
                uint32_t ao = (uint32_t)((MB + mt * 16 + a_r) * PITCH + kk * 16 + a_k) * 2;
                ldsm_x4(Afh[mt][0], Afh[mt][1], Afh[mt][2], Afh[mt][3], bb + 0 * TERM_BYTES + ao);
                ldsm_x4(Afl[mt][0], Afl[mt][1], Afl[mt][2], Afl[mt][3], bb + 1 * TERM_BYTES + ao);
            }
#pragma unroll
            for (int nt = 0; nt < 4; nt++) {
                uint32_t bo = (uint32_t)((NB + nt * 8 + b_r) * PITCH + kk * 16 + b_k) * 2;
                ldsm_x2(Bfh[nt][0], Bfh[nt][1], bb + 2 * TERM_BYTES + bo);
                ldsm_x2(Bfl[nt][0], Bfl[nt][1], bb + 3 * TERM_BYTES + bo);
            }
#pragma unroll
            for (int mt = 0; mt < 4; mt++)
#pragma unroll
                for (int nt = 0; nt < 4; nt++) {
                    mma16816(acc[mt][nt], Afh[mt], Bfh[nt]);
                    mma16816(acc[mt][nt], Afh[mt], Bfl[nt]);
                    mma16816(acc[mt][nt], Afl[mt], Bfh[nt]);
                }
        }
        __syncthreads();
        buf ^= 1;
    }

    int g = lane >> 2, tig = lane & 3;
#pragma unroll
    for (int mt = 0; mt < 4; mt++)
#pragma unroll
        for (int nt = 0; nt < 4; nt++) {
            int row0 = m0 + MB + mt * 16 + g;
            int row1 = row0 + 8;
            int cb = n0 + NB + nt * 8 + tig * 2;
#pragma unroll
            for (int e = 0; e < 2; e++) {
                int n = cb + e;
                float v0 = acc[mt][nt][e];
                float v1 = acc[mt][nt][2 + e];
                if (REMAP) {
                    int c = n % 3;
                    int ix = n / 3;
                    float* dst = (c == 0) ? g_q : (c == 1) ? g_k : g_v;
                    dst[(size_t)row0 * D_MODEL + ix] = v0;
                    dst[(size_t)row1 * D_MODEL + ix] = v1;
                } else {
                    C[(size_t)row0 * D_MODEL + n] = v0;
                    C[(size_t)row1 * D_MODEL + n] = v1;
                }
            }
        }
}

// ---------------------------------------------------------------------------
// RoPE: read fp32 g_q/g_k, write rotated values as bf16 hi/lo splits.
// ---------------------------------------------------------------------------
__device__ __forceinline__ void split_store(__nv_bfloat16* hi, __nv_bfloat16* lo,
                                            size_t idx, float v) {
    __nv_bfloat16 h = __float2bfloat16(v);
    hi[idx] = h;
    lo[idx] = __float2bfloat16(v - __bfloat162float(h));
}

__global__ void rope_split_kernel() {
    int idx = blockIdx.x * blockDim.x + threadIdx.x;
    if (idx >= S_LEN * NH * 64) return;
    int i = idx & 63;
    int h = (idx >> 6) & (NH - 1);
    int s = idx >> 11;
    float inv_freq = expf(-0.14391156831212787f * (float)i);
    float ang = (float)s * inv_freq;
    float sn, c;
    sincosf(ang, &sn, &c);
    size_t base = (size_t)s * D_MODEL + (size_t)h * HD + i;
    float q1 = g_q[base], q2 = g_q[base + 64];
    split_store(g_qh, g_ql, base,      q1 * c - q2 * sn);
    split_store(g_qh, g_ql, base + 64, q2 * c + q1 * sn);
    float k1 = g_k[base], k2 = g_k[base + 64];
    split_store(g_kh, g_kl, base,      k1 * c - k2 * sn);
    split_store(g_kh, g_kl, base + 64, k2 * c + k1 * sn);
}

// ---------------------------------------------------------------------------
// Tensor-core flash attention (split-bf16, causal).
// CTA = (64 q-rows, head), 256 threads, 8 warps as 4m x 2n.
// ---------------------------------------------------------------------------
#define FP 136   // Q/K/V smem pitch in bf16 (272 B)
#define PP 72    // P smem pitch in bf16 (144 B)
#define QH_OFF 0
#define QL_OFF 17408
#define KH_OFF 34816
#define KL_OFF 52224
#define VH_OFF 69632
#define VL_OFF 87040
#define PH_OFF 104448
#define PL_OFF 113664
#define ST_OFF 122880
#define FLASH2_SMEM 124672

__global__ void __launch_bounds__(256) flash_mma_kernel() {
    extern __shared__ char smc[];
    uint32_t sb = smem_u32(smc);
    __nv_bfloat16* Qh = (__nv_bfloat16*)(smc + QH_OFF);
    __nv_bfloat16* Ql = (__nv_bfloat16*)(smc + QL_OFF);
    __nv_bfloat16* Kh = (__nv_bfloat16*)(smc + KH_OFF);
    __nv_bfloat16* Kl = (__nv_bfloat16*)(smc + KL_OFF);
    __nv_bfloat16* Vh = (__nv_bfloat16*)(smc + VH_OFF);
    __nv_bfloat16* Vl = (__nv_bfloat16*)(smc + VL_OFF);
    float* sM   = (float*)(smc + ST_OFF);          // [64]
    float* sL   = sM + 64;                         // [64]
    float* sAl  = sM + 128;                        // [64]
    float* sPart = sM + 192;                       // [2][64]
    float* sSum  = sM + 320;                       // [2][64]
    __nv_bfloat162* Phw = (__nv_bfloat162*)(smc + PH_OFF);
    __nv_bfloat162* Plw = (__nv_bfloat162*)(smc + PL_OFF);

    int tid = threadIdx.x;
    int lane = tid & 31;
    int wid = tid >> 5;
    int wm = wid >> 1;             // 0..3
    int wn = wid & 1;              // 0..1
    int qt = (int)gridDim.x - 1 - (int)blockIdx.x;  // heavy tiles first
    int h = blockIdx.y;
    int q0 = qt * 64;

    // Load Q tile (hi/lo).
#pragma unroll
    for (int it = 0; it < 4; it++) {
        int s = tid + it * 256;
        int r = s >> 4;
        int c = (s & 15) * 8;
        size_t g = (size_t)(q0 + r) * D_MODEL + (size_t)h * HD + c;
        *(uint4*)(Qh + r * FP + c) = *(const uint4*)(g_qh + g);
        *(uint4*)(Ql + r * FP + c) = *(const uint4*)(g_ql + g);
    }
    if (tid < 64) { sM[tid] = -INFINITY; sL[tid] = 0.f; }

    float o[8][4];
#pragma unroll
    for (int i = 0; i < 8; i++)
#pragma unroll
        for (int j = 0; j < 4; j++) o[i][j] = 0.f;

    int g_ = lane >> 2, tig = lane & 3;
    int a_r = (lane & 7) | (((lane >> 3) & 1) << 3);
    int a_k = (lane >> 4) << 3;
    int b_r = lane & 7;
    int b_k = ((lane >> 3) & 1) << 3;
    int vrow = lane & 15;
    int r0 = wm * 16 + g_, r1 = r0 + 8;
    const float scale = 0.08838834764831845f;

    __syncthreads();

    for (int kt = 0; kt <= qt; kt++) {
        int k0 = kt * 64;
        // Load K/V tiles (hi/lo).
#pragma unroll
        for (int it = 0; it < 4; it++) {
            int s = tid + it * 256;
            int r = s >> 4;
            int c = (s & 15) * 8;
            size_t g = (size_t)(k0 + r) * D_MODEL + (size_t)h * HD + c;
            *(uint4*)(Kh + r * FP + c) = *(const uint4*)(g_kh + g);
            *(uint4*)(Kl + r * FP + c) = *(const uint4*)(g_kl + g);
            *(uint4*)(Vh + r * FP + c) = *(const uint4*)(g_vh + g);
            *(uint4*)(Vl + r * FP + c) = *(const uint4*)(g_vl + g);
        }
        __syncthreads();

        // S = Q K^T (3-term split-bf16), warp tile m16 x n32.
        float s4[4][4];
#pragma unroll
        for (int nt = 0; nt < 4; nt++)
#pragma unroll
            for (int e = 0; e < 4; e++) s4[nt][e] = 0.f;

#pragma unroll
        for (int kk = 0; kk < 8; kk++) {
            uint32_t Afh[4], Afl[4];
            uint32_t ao = (uint32_t)((wm * 16 + a_r) * FP + kk * 16 + a_k) * 2;
            ldsm_x4(Afh[0], Afh[1], Afh[2], Afh[3], sb + QH_OFF + ao);
            ldsm_x4(Afl[0], Afl[1], Afl[2], Afl[3], sb + QL_OFF + ao);
#pragma unroll
            for (int nt = 0; nt < 4; nt++) {
                uint32_t Bh[2], Bl[2];
                uint32_t bo = (uint32_t)((wn * 32 + nt * 8 + b_r) * FP + kk * 16 + b_k) * 2;
                ldsm_x2(Bh[0], Bh[1], sb + KH_OFF + bo);
                ldsm_x2(Bl[0], Bl[1], sb + KL_OFF + bo);
                mma16816(s4[nt], Afh, Bh);
                mma16816(s4[nt], Afh, Bl);
                mma16816(s4[nt], Afl, Bh);
            }
        }

        bool diag = (kt == qt);
#pragma unroll
        for (int nt = 0; nt < 4; nt++)
#pragma unroll
            for (int e = 0; e < 4; e++) {
                s4[nt][e] *= scale;
                if (diag) {
                    int row_in = wm * 16 + g_ + ((e >= 2) ? 8 : 0);
                    int col_in = wn * 32 + nt * 8 + tig * 2 + (e & 1);
                    if (col_in > row_in) s4[nt][e] = -INFINITY;
                }
            }

        // Row max: quad reduce, then cross-warp via smem.
        float mx0 = -INFINITY, mx1 = -INFINITY;
#pragma unroll
        for (int nt = 0; nt < 4; nt++) {
            mx0 = fmaxf(mx0, fmaxf(s4[nt][0], s4[nt][1]));
            mx1 = fmaxf(mx1, fmaxf(s4[nt][2], s4[nt][3]));
        }
        mx0 = fmaxf(mx0, __shfl_xor_sync(0xffffffffu, mx0, 1));
        mx0 = fmaxf(mx0, __shfl_xor_sync(0xffffffffu, mx0, 2));
        mx1 = fmaxf(mx1, __shfl_xor_sync(0xffffffffu, mx1, 1));
        mx1 = fmaxf(mx1, __shfl_xor_sync(0xffffffffu, mx1, 2));
        if (tig == 0) {
            sPart[wn * 64 + r0] = mx0;
            sPart[wn * 64 + r1] = mx1;
        }
        __syncthreads();

        if (tid < 64) {
            float mnew = fmaxf(sM[tid], fmaxf(sPart[tid], sPart[64 + tid]));
            sAl[tid] = __expf(sM[tid] - mnew);
            sM[tid] = mnew;
        }
        __syncthreads();

        // exp, row sums, P -> smem bf16 hi/lo; rescale O by alpha.
        float mn0 = sM[r0], mn1 = sM[r1];
        float su0 = 0.f, su1 = 0.f;
#pragma unroll
        for (int nt = 0; nt < 4; nt++) {
            float p0 = __expf(s4[nt][0] - mn0);
            float p1 = __expf(s4[nt][1] - mn0);
            float p2 = __expf(s4[nt][2] - mn1);
            float p3 = __expf(s4[nt][3] - mn1);
            su0 += p0 + p1;
            su1 += p2 + p3;
            __nv_bfloat16 h0 = __float2bfloat16(p0), h1 = __float2bfloat16(p1);
            __nv_bfloat16 h2 = __float2bfloat16(p2), h3 = __float2bfloat16(p3);
            __nv_bfloat16 l0 = __float2bfloat16(p0 - __bfloat162float(h0));
            __nv_bfloat16 l1 = __float2bfloat16(p1 - __bfloat162float(h1));
            __nv_bfloat16 l2 = __float2bfloat16(p2 - __bfloat162float(h2));
            __nv_bfloat16 l3 = __float2bfloat16(p3 - __bfloat162float(h3));
            int cp = (wn * 32 + nt * 8 + tig * 2) >> 1;
            Phw[(r0 * PP >> 1) + cp] = __halves2bfloat162(h0, h1);
            Phw[(r1 * PP >> 1) + cp] = __halves2bfloat162(h2, h3);
            Plw[(r0 * PP >> 1) + cp] = __halves2bfloat162(l0, l1);
            Plw[(r1 * PP >> 1) + cp] = __halves2bfloat162(l2, l3);
        }
        su0 += __shfl_xor_sync(0xffffffffu, su0, 1);
        su0 += __shfl_xor_sync(0xffffffffu, su0, 2);
        su1 += __shfl_xor_sync(0xffffffffu, su1, 1);
        su1 += __shfl_xor_sync(0xffffffffu, su1, 2);
        if (tig == 0) {
            sSum[wn * 64 + r0] = su0;
            sSum[wn * 64 + r1] = su1;
        }
        float al0 = sAl[r0], al1 = sAl[r1];
#pragma unroll
        for (int nt = 0; nt < 8; nt++) {
            o[nt][0] *= al0;
            o[nt][1] *= al0;
            o[nt][2] *= al1;
            o[nt][3] *= al1;
        }
        __syncthreads();

        if (tid < 64) sL[tid] = sL[tid] * sAl[tid] + sSum[tid] + sSum[64 + tid];

        // O += P V (3-term), warp tile m16 x n64.
#pragma unroll
        for (int kk = 0; kk < 4; kk++) {
            uint32_t Pfh[4], Pfl[4];
            uint32_t ao = (uint32_t)((wm * 16 + a_r) * PP + kk * 16 + a_k) * 2;
            ldsm_x4(Pfh[0], Pfh[1], Pfh[2], Pfh[3], sb + PH_OFF + ao);
            ldsm_x4(Pfl[0], Pfl[1], Pfl[2], Pfl[3], sb + PL_OFF + ao);
#pragma unroll
            for (int nt = 0; nt < 8; nt++) {
                uint32_t Vhf[2], Vlf[2];
                uint32_t vo = (uint32_t)((kk * 16 + vrow) * FP + wn * 64 + nt * 8) * 2;
                ldsm_x2t(Vhf[0], Vhf[1], sb + VH_OFF + vo);
                ldsm_x2t(Vlf[0], Vlf[1], sb + VL_OFF + vo);
                mma16816(o[nt], Pfh, Vhf);
                mma16816(o[nt], Pfh, Vlf);
                mma16816(o[nt], Pfl, Vhf);
            }
        }
        __syncthreads();
    }

    // Normalize and store context.
    float inv0 = 1.f / sL[r0];
    float inv1 = 1.f / sL[r1];
#pragma unroll
    for (int nt = 0; nt < 8; nt++) {
        int col = wn * 64 + nt * 8 + tig * 2;
        size_t b0 = (size_t)(q0 + r0) * D_MODEL + (size_t)h * HD + col;
        size_t b1 = (size_t)(q0 + r1) * D_MODEL + (size_t)h * HD + col;
        g_ctx[b0]     = o[nt][0] * inv0;
        g_ctx[b0 + 1] = o[nt][1] * inv0;
        g_ctx[b1]     = o[nt][2] * inv1;
        g_ctx[b1 + 1] = o[nt][3] * inv1;
    }
}

// ---------------------------------------------------------------------------
extern "C" void kernel_launch(void* const* d_in, const int* in_sizes, int n_in,
                              void* d_out, int out_size) {
    const float* hidden = (const float*)d_in[0];
    const float* Wqkv = (const float*)d_in[3];
    const float* Wo   = (const float*)d_in[4];
    float* out = (float*)d_out;

    cudaFuncSetAttribute(gemm_mma_kernel<1>, cudaFuncAttributeMaxDynamicSharedMemorySize, GEMM_SMEM);
    cudaFuncSetAttribute(gemm_mma_kernel<0>, cudaFuncAttributeMaxDynamicSharedMemorySize, GEMM_SMEM);
    cudaFuncSetAttribute(flash_mma_kernel, cudaFuncAttributeMaxDynamicSharedMemorySize, FLASH2_SMEM);

    void *p_ah, *p_al, *p_wqh, *p_wql, *p_woh, *p_wol, *p_cth, *p_ctl, *p_ctx, *p_v, *p_vh, *p_vl;
    cudaGetSymbolAddress(&p_ah, g_ah);
    cudaGetSymbolAddress(&p_al, g_al);
    cudaGetSymbolAddress(&p_wqh, g_wqkvT_h);
    cudaGetSymbolAddress(&p_wql, g_wqkvT_l);
    cudaGetSymbolAddress(&p_woh, g_woT_h);
    cudaGetSymbolAddress(&p_wol, g_woT_l);
    cudaGetSymbolAddress(&p_cth, g_cth);
    cudaGetSymbolAddress(&p_ctl, g_ctl);
    cudaGetSymbolAddress(&p_ctx, g_ctx);
    cudaGetSymbolAddress(&p_v, g_v);
    cudaGetSymbolAddress(&p_vh, g_vh);
    cudaGetSymbolAddress(&p_vl, g_vl);

    // 1) split hidden, split+transpose weights
    split_rows_kernel<<<(S_LEN * D_MODEL / 4 + 255) / 256, 256>>>(
        hidden, (__nv_bfloat16*)p_ah, (__nv_bfloat16*)p_al, S_LEN * D_MODEL / 4);
    split_transpose_kernel<<<dim3(3 * D_MODEL / 32, D_MODEL / 32), dim3(32, 8)>>>(
        Wqkv, (__nv_bfloat16*)p_wqh, (__nv_bfloat16*)p_wql, D_MODEL, 3 * D_MODEL);
    split_transpose_kernel<<<dim3(D_MODEL / 32, D_MODEL / 32), dim3(32, 8)>>>(
        Wo, (__nv_bfloat16*)p_woh, (__nv_bfloat16*)p_wol, D_MODEL, D_MODEL);

    // 2) QKV projection (HMMA, remap into g_q/g_k/g_v fp32)
    gemm_mma_kernel<1><<<dim3(16, 96), 256, GEMM_SMEM>>>(
        (const __nv_bfloat16*)p_ah, (const __nv_bfloat16*)p_al,
        (const __nv_bfloat16*)p_wqh, (const __nv_bfloat16*)p_wql, nullptr);

    // 3) RoPE -> bf16 hi/lo splits of Q,K ; split V
    rope_split_kernel<<<(S_LEN * NH * 64 + 255) / 256, 256>>>();
    split_rows_kernel<<<(S_LEN * D_MODEL / 4 + 255) / 256, 256>>>(
        (const float*)p_v, (__nv_bfloat16*)p_vh, (__nv_bfloat16*)p_vl, S_LEN * D_MODEL / 4);

    // 4) Tensor-core flash attention
    flash_mma_kernel<<<dim3(S_LEN / 64, NH), 256, FLASH2_SMEM>>>();

    // 5) split ctx, output projection (HMMA)
    split_rows_kernel<<<(S_LEN * D_MODEL / 4 + 255) / 256, 256>>>(
        (const float*)p_ctx, (__nv_bfloat16*)p_cth, (__nv_bfloat16*)p_ctl, S_LEN * D_MODEL / 4);
    gemm_mma_kernel<0><<<dim3(16, 32), 256, GEMM_SMEM>>>(
        (const __nv_bfloat16*)p_cth, (const __nv_bfloat16*)p_ctl,
        (const __nv_bfloat16*)p_woh, (const __nv_bfloat16*)p_wol, out);
}